// round 8
// baseline (speedup 1.0000x reference)
#include <cuda_runtime.h>
#include <cuda_fp16.h>
#include <cstdint>

namespace {

constexpr int ATOM = 128;
constexpr int BOND = 64;
constexpr int KTOT = 192;    // 48 float4 per row
constexpr int NOUT = 256;
constexpr int BM   = 128;    // edges per tile
constexpr int NTHREADS = 512;
constexpr int STRIDE = 100;  // tile row stride (words); 100%32=4 -> ldmatrix conflict-free

// smem layout (4B words): B first, then two A buffers
constexpr int SM_B_W  = 0;                        // 256 x 100
constexpr int SM_A0_W = NOUT * STRIDE;            // 128 x 100
constexpr int SM_A1_W = SM_A0_W + BM * STRIDE;
constexpr int SMEM_BYTES = (SM_A1_W + BM * STRIDE) * 4;   // 204800

// per-warp epilogue staging slot (inside the dead A buffer)
constexpr int SLOT_STRIDE = 40;                   // words; STS.64/LDS.128 conflict-free
constexpr int SLOT_WORDS  = 16 * SLOT_STRIDE;     // 640; 16 warps -> 10240 <= 12800

__device__ __forceinline__ uint32_t h2(float lo, float hi) {
    __half2 h = __floats2half2_rn(lo, hi);
    return *(uint32_t*)&h;
}

#define LDM_X4(r0, r1, r2, r3, addr)                                          \
    asm volatile("ldmatrix.sync.aligned.m8n8.x4.shared.b16 {%0,%1,%2,%3}, [%4];" \
                 : "=r"(r0), "=r"(r1), "=r"(r2), "=r"(r3) : "r"(addr))

__global__ void __launch_bounds__(NTHREADS, 1)
bond_msg_kernel(const float* __restrict__ V,
                const float* __restrict__ E,
                const int* __restrict__ src0,      // edge_index row 0 (int32)
                const float* __restrict__ W,       // [NOUT, KTOT]
                const float* __restrict__ bias,    // [NOUT]
                float* __restrict__ out,           // [M, NOUT]
                int M, int ntiles)
{
    extern __shared__ uint32_t smem[];
    uint32_t* Bs = smem + SM_B_W;
    uint32_t* Abuf[2] = { smem + SM_A0_W, smem + SM_A1_W };

    uint32_t sb;   // smem byte base
    asm("{ .reg .u64 t; cvta.to.shared.u64 t, %1; cvt.u32.u64 %0, t; }"
        : "=r"(sb) : "l"((const void*)smem));

    const int tid  = threadIdx.x;
    const int lane = tid & 31;
    const int wid  = tid >> 5;
    const int warp_m = wid >> 2;   // 0..3 (32 rows each)
    const int warp_n = wid & 3;    // 0..3 (64 cols each)
    const int lr = lane >> 2;
    const int lc = lane & 3;
    const int G  = gridDim.x;

    // ---- ldmatrix per-thread address offsets (word units)
    uint32_t a_off_w[2];
    #pragma unroll
    for (int mi = 0; mi < 2; ++mi) {
        int arow = warp_m * 32 + mi * 16 + (lane & 7) + 8 * ((lane >> 3) & 1);
        a_off_w[mi] = (uint32_t)(arow * STRIDE + 4 * (lane >> 4));
    }
    uint32_t b_addr0[4];
    #pragma unroll
    for (int p = 0; p < 4; ++p) {
        int brow = warp_n * 64 + p * 16 + (lane & 7) + 8 * (lane >> 4);
        b_addr0[p] = sb + 4u * (uint32_t)(SM_B_W + brow * STRIDE + 4 * ((lane >> 3) & 1));
    }

    // ---- bias fragments for the staged epilogue (2 float4 per thread)
    float4 bias_v[2];
    #pragma unroll
    for (int nh = 0; nh < 2; ++nh)
        bias_v[nh] = *(const float4*)(bias + warp_n * 64 + nh * 32 + (lane & 7) * 4);

    // ---- Fill W once per CTA (persistent): 12288 float4, 24 per thread.
    #pragma unroll
    for (int i = 0; i < 24; ++i) {
        int idx = tid + i * NTHREADS;
        int n  = idx / 48;
        int c4 = idx % 48;
        float4 v = *(const float4*)(W + (size_t)n * KTOT + c4 * 4);
        uint32_t* d = Bs + n * STRIDE + c4 * 2;
        d[0] = h2(v.x, v.y);
        d[1] = h2(v.z, v.w);
    }

    // ---- Prologue: fill A[0] for the first tile.
    int t0 = blockIdx.x;
    if (t0 < ntiles) {
        int e0 = t0 * BM;
        #pragma unroll
        for (int i = 0; i < 12; ++i) {
            int idx = tid + i * NTHREADS;
            int r  = idx / 48;
            int c4 = idx % 48;
            int e  = e0 + r; if (e >= M) e = M - 1;
            const float* p = (c4 < 32)
                ? (V + (size_t)__ldg(src0 + e) * ATOM + c4 * 4)
                : (E + (size_t)e * BOND + (c4 - 32) * 4);
            float4 v = *(const float4*)p;
            uint32_t* d = Abuf[0] + r * STRIDE + c4 * 2;
            d[0] = h2(v.x, v.y);
            d[1] = h2(v.z, v.w);
        }
    }
    __syncthreads();

    int cur = 0;
    for (int t = t0; t < ntiles; t += G) {
        const int e0  = t * BM;
        const int tn  = t + G;
        const bool hn = (tn < ntiles);
        const int e0n = tn * BM;
        uint32_t* An = Abuf[cur ^ 1];

        const uint32_t abase = sb + 4u * (uint32_t)(cur ? SM_A1_W : SM_A0_W);
        uint32_t aaddr[2] = { abase + 4u * a_off_w[0], abase + 4u * a_off_w[1] };
        uint32_t baddr[4] = { b_addr0[0], b_addr0[1], b_addr0[2], b_addr0[3] };

        float acc[2][8][4];
        #pragma unroll
        for (int mi = 0; mi < 2; ++mi)
            #pragma unroll
            for (int ni = 0; ni < 8; ++ni)
                #pragma unroll
                for (int c = 0; c < 4; ++c)
                    acc[mi][ni][c] = 0.f;

        // 3 pipeline stages: prefetch batch b (4 float4) -> 4 MMA k-steps -> STS batch b
        #pragma unroll
        for (int b = 0; b < 3; ++b) {
            float4 g[4];
            if (hn) {
                #pragma unroll
                for (int i = 0; i < 4; ++i) {
                    int idx = tid + (b * 4 + i) * NTHREADS;
                    int r  = idx / 48;
                    int c4 = idx % 48;
                    int e  = e0n + r; if (e >= M) e = M - 1;
                    const float* p = (c4 < 32)
                        ? (V + (size_t)__ldg(src0 + e) * ATOM + c4 * 4)
                        : (E + (size_t)e * BOND + (c4 - 32) * 4);
                    g[i] = *(const float4*)p;
                }
            }

            #pragma unroll
            for (int kk = 0; kk < 4; ++kk) {
                uint32_t a[2][4], bf[8][2];
                LDM_X4(a[0][0], a[0][1], a[0][2], a[0][3], aaddr[0]);
                LDM_X4(a[1][0], a[1][1], a[1][2], a[1][3], aaddr[1]);
                #pragma unroll
                for (int p = 0; p < 4; ++p) {
                    LDM_X4(bf[2*p][0], bf[2*p][1], bf[2*p+1][0], bf[2*p+1][1],
                           baddr[p]);
                    baddr[p] += 32;      // +8 words per k-step
                }
                aaddr[0] += 32;
                aaddr[1] += 32;

                #pragma unroll
                for (int mi = 0; mi < 2; ++mi)
                    #pragma unroll
                    for (int ni = 0; ni < 8; ++ni) {
                        asm volatile(
                            "mma.sync.aligned.m16n8k16.row.col.f32.f16.f16.f32 "
                            "{%0,%1,%2,%3}, {%4,%5,%6,%7}, {%8,%9}, {%0,%1,%2,%3};\n"
                            : "+f"(acc[mi][ni][0]), "+f"(acc[mi][ni][1]),
                              "+f"(acc[mi][ni][2]), "+f"(acc[mi][ni][3])
                            : "r"(a[mi][0]), "r"(a[mi][1]),
                              "r"(a[mi][2]), "r"(a[mi][3]),
                              "r"(bf[ni][0]), "r"(bf[ni][1]));
                    }
            }

            if (hn) {
                #pragma unroll
                for (int i = 0; i < 4; ++i) {
                    int idx = tid + (b * 4 + i) * NTHREADS;
                    int r  = idx / 48;
                    int c4 = idx % 48;
                    uint32_t* d = An + r * STRIDE + c4 * 2;
                    d[0] = h2(g[i].x, g[i].y);
                    d[1] = h2(g[i].z, g[i].w);
                }
            }
        }

        // All warps must be done ldmatrix-reading Abuf[cur] before any warp
        // stages accumulators into it (cross-warp WAR race -> NaN in round 7).
        __syncthreads();

        // ---- Staged epilogue: per-warp slot in the now-dead Abuf[cur].
        uint32_t* slot = Abuf[cur] + wid * SLOT_WORDS;
        #pragma unroll
        for (int q = 0; q < 4; ++q) {
            const int mi = q >> 1;
            const int nh = q & 1;
            #pragma unroll
            for (int j = 0; j < 4; ++j) {
                const int ni = 4 * nh + j;
                const int col = j * 8 + 2 * lc;
                *(float2*)(slot + lr * SLOT_STRIDE + col) =
                    make_float2(acc[mi][ni][0], acc[mi][ni][1]);
                *(float2*)(slot + (lr + 8) * SLOT_STRIDE + col) =
                    make_float2(acc[mi][ni][2], acc[mi][ni][3]);
            }
            __syncwarp();
            #pragma unroll
            for (int i = 0; i < 4; ++i) {
                const int srow = 4 * i + (lane >> 3);
                const int scol = (lane & 7) * 4;
                float4 v = *(float4*)(slot + srow * SLOT_STRIDE + scol);
                v.x += bias_v[nh].x; v.y += bias_v[nh].y;
                v.z += bias_v[nh].z; v.w += bias_v[nh].w;
                const int grow = e0 + warp_m * 32 + mi * 16 + srow;
                if (grow < M)
                    *(float4*)(out + (size_t)grow * NOUT
                               + warp_n * 64 + nh * 32 + scol) = v;
            }
            __syncwarp();
        }

        __syncthreads();     // An fully written; staging consumed
        cur ^= 1;
    }
}

} // namespace

extern "C" void kernel_launch(void* const* d_in, const int* in_sizes, int n_in,
                              void* d_out, int out_size)
{
    const float* V   = (const float*)d_in[0];
    const float* E   = (const float*)d_in[1];
    const int*   EI  = (const int*)d_in[2];   // int32 (JAX canonicalized), row 0 = src
    const float* W   = (const float*)d_in[3];
    const float* b   = (const float*)d_in[4];
    float*       out = (float*)d_out;

    const int M = in_sizes[1] / BOND;
    const int ntiles = (M + BM - 1) / BM;

    int sms = 148;
    cudaDeviceGetAttribute(&sms, cudaDevAttrMultiProcessorCount, 0);
    int grid = sms < ntiles ? sms : ntiles;

    cudaFuncSetAttribute(bond_msg_kernel,
                         cudaFuncAttributeMaxDynamicSharedMemorySize, SMEM_BYTES);
    bond_msg_kernel<<<grid, NTHREADS, SMEM_BYTES>>>(V, E, EI, W, b, out, M, ntiles);
}

// round 9
// speedup vs baseline: 1.0222x; 1.0222x over previous
#include <cuda_runtime.h>
#include <cuda_fp16.h>
#include <cstdint>

namespace {

constexpr int ATOM = 128;
constexpr int BOND = 64;
constexpr int KTOT = 192;    // 48 float4 per row
constexpr int NOUT = 256;
constexpr int BM   = 128;    // edges per tile
constexpr int NTHREADS = 512;
constexpr int STRIDE = 100;  // tile row stride (words); 100%32=4 -> ldmatrix conflict-free

// smem layout (4B words): B first, then two A buffers
constexpr int SM_B_W  = 0;                        // 256 x 100
constexpr int SM_A0_W = NOUT * STRIDE;            // 128 x 100
constexpr int SM_A1_W = SM_A0_W + BM * STRIDE;
constexpr int SMEM_BYTES = (SM_A1_W + BM * STRIDE) * 4;   // 204800

__device__ __forceinline__ uint32_t h2(float lo, float hi) {
    __half2 h = __floats2half2_rn(lo, hi);
    return *(uint32_t*)&h;
}

#define LDM_X4(r0, r1, r2, r3, addr)                                          \
    asm volatile("ldmatrix.sync.aligned.m8n8.x4.shared.b16 {%0,%1,%2,%3}, [%4];" \
                 : "=r"(r0), "=r"(r1), "=r"(r2), "=r"(r3) : "r"(addr))

__global__ void __launch_bounds__(NTHREADS, 1)
bond_msg_kernel(const float* __restrict__ V,
                const float* __restrict__ E,
                const int* __restrict__ src0,      // edge_index row 0 (int32)
                const float* __restrict__ W,       // [NOUT, KTOT]
                const float* __restrict__ bias,    // [NOUT]
                float* __restrict__ out,           // [M, NOUT]
                int M, int ntiles)
{
    extern __shared__ uint32_t smem[];
    uint32_t* Bs = smem + SM_B_W;
    uint32_t* Abuf[2] = { smem + SM_A0_W, smem + SM_A1_W };

    uint32_t sb;   // smem byte base
    asm("{ .reg .u64 t; cvta.to.shared.u64 t, %1; cvt.u32.u64 %0, t; }"
        : "=r"(sb) : "l"((const void*)smem));

    const int tid  = threadIdx.x;
    const int lane = tid & 31;
    const int wid  = tid >> 5;
    const int warp_m = wid >> 2;   // 0..3 (32 rows each)
    const int warp_n = wid & 3;    // 0..3 (64 cols each)
    const int lr = lane >> 2;
    const int lc = lane & 3;
    const int G  = gridDim.x;

    // ---- ldmatrix per-thread address offsets (word units) — proven in R8
    uint32_t a_off_w[2];
    #pragma unroll
    for (int mi = 0; mi < 2; ++mi) {
        int arow = warp_m * 32 + mi * 16 + (lane & 7) + 8 * ((lane >> 3) & 1);
        a_off_w[mi] = (uint32_t)(arow * STRIDE + 4 * (lane >> 4));
    }
    uint32_t b_addr0[4];
    #pragma unroll
    for (int p = 0; p < 4; ++p) {
        int brow = warp_n * 64 + p * 16 + (lane & 7) + 8 * (lane >> 4);
        b_addr0[p] = sb + 4u * (uint32_t)(SM_B_W + brow * STRIDE + 4 * ((lane >> 3) & 1));
    }

    // ---- Fill W once per CTA (persistent): 12288 float4, 24 per thread.
    #pragma unroll
    for (int i = 0; i < 24; ++i) {
        int idx = tid + i * NTHREADS;
        int n  = idx / 48;
        int c4 = idx % 48;
        float4 v = *(const float4*)(W + (size_t)n * KTOT + c4 * 4);
        uint32_t* d = Bs + n * STRIDE + c4 * 2;
        d[0] = h2(v.x, v.y);
        d[1] = h2(v.z, v.w);
    }

    // ---- Prologue: fill A[0] for the first tile.
    int t0 = blockIdx.x;
    if (t0 < ntiles) {
        int e0 = t0 * BM;
        #pragma unroll
        for (int i = 0; i < 12; ++i) {
            int idx = tid + i * NTHREADS;
            int r  = idx / 48;
            int c4 = idx % 48;
            int e  = e0 + r; if (e >= M) e = M - 1;
            const float* p = (c4 < 32)
                ? (V + (size_t)__ldg(src0 + e) * ATOM + c4 * 4)
                : (E + (size_t)e * BOND + (c4 - 32) * 4);
            float4 v = *(const float4*)p;
            uint32_t* d = Abuf[0] + r * STRIDE + c4 * 2;
            d[0] = h2(v.x, v.y);
            d[1] = h2(v.z, v.w);
        }
    }
    __syncthreads();

    int cur = 0;
    for (int t = t0; t < ntiles; t += G) {
        const int e0  = t * BM;
        const int tn  = t + G;
        const bool hn = (tn < ntiles);
        const int e0n = tn * BM;
        uint32_t* An = Abuf[cur ^ 1];

        const uint32_t abase = sb + 4u * (uint32_t)(cur ? SM_A1_W : SM_A0_W);
        uint32_t aaddr[2] = { abase + 4u * a_off_w[0], abase + 4u * a_off_w[1] };
        uint32_t baddr[4] = { b_addr0[0], b_addr0[1], b_addr0[2], b_addr0[3] };

        float acc[2][8][4];
        #pragma unroll
        for (int mi = 0; mi < 2; ++mi)
            #pragma unroll
            for (int ni = 0; ni < 8; ++ni)
                #pragma unroll
                for (int c = 0; c < 4; ++c)
                    acc[mi][ni][c] = 0.f;

        // 3 pipeline stages: prefetch batch b (4 float4) -> 4 MMA k-steps -> STS batch b
        #pragma unroll
        for (int b = 0; b < 3; ++b) {
            float4 g[4];
            if (hn) {
                #pragma unroll
                for (int i = 0; i < 4; ++i) {
                    int idx = tid + (b * 4 + i) * NTHREADS;
                    int r  = idx / 48;
                    int c4 = idx % 48;
                    int e  = e0n + r; if (e >= M) e = M - 1;
                    const float* p = (c4 < 32)
                        ? (V + (size_t)__ldg(src0 + e) * ATOM + c4 * 4)
                        : (E + (size_t)e * BOND + (c4 - 32) * 4);
                    g[i] = *(const float4*)p;
                }
            }

            #pragma unroll
            for (int kk = 0; kk < 4; ++kk) {
                uint32_t a[2][4], bf[8][2];
                LDM_X4(a[0][0], a[0][1], a[0][2], a[0][3], aaddr[0]);
                LDM_X4(a[1][0], a[1][1], a[1][2], a[1][3], aaddr[1]);
                #pragma unroll
                for (int p = 0; p < 4; ++p) {
                    LDM_X4(bf[2*p][0], bf[2*p][1], bf[2*p+1][0], bf[2*p+1][1],
                           baddr[p]);
                    baddr[p] += 32;      // +8 words per k-step
                }
                aaddr[0] += 32;
                aaddr[1] += 32;

                #pragma unroll
                for (int mi = 0; mi < 2; ++mi)
                    #pragma unroll
                    for (int ni = 0; ni < 8; ++ni) {
                        asm volatile(
                            "mma.sync.aligned.m16n8k16.row.col.f32.f16.f16.f32 "
                            "{%0,%1,%2,%3}, {%4,%5,%6,%7}, {%8,%9}, {%0,%1,%2,%3};\n"
                            : "+f"(acc[mi][ni][0]), "+f"(acc[mi][ni][1]),
                              "+f"(acc[mi][ni][2]), "+f"(acc[mi][ni][3])
                            : "r"(a[mi][0]), "r"(a[mi][1]),
                              "r"(a[mi][2]), "r"(a[mi][3]),
                              "r"(bf[ni][0]), "r"(bf[ni][1]));
                    }
            }

            if (hn) {
                #pragma unroll
                for (int i = 0; i < 4; ++i) {
                    int idx = tid + (b * 4 + i) * NTHREADS;
                    int r  = idx / 48;
                    int c4 = idx % 48;
                    uint32_t* d = An + r * STRIDE + c4 * 2;
                    d[0] = h2(g[i].x, g[i].y);
                    d[1] = h2(g[i].z, g[i].w);
                }
            }
        }

        // ---- Direct epilogue (round-6 proven): fire-and-forget float2 STGs,
        // no smem touched, no barrier needed before it.
        #pragma unroll
        for (int mi = 0; mi < 2; ++mi) {
            int row0 = e0 + warp_m * 32 + mi * 16 + lr;
            int row1 = row0 + 8;
            #pragma unroll
            for (int ni = 0; ni < 8; ++ni) {
                int col = warp_n * 64 + ni * 8 + 2 * lc;
                float2 bb = *(const float2*)(bias + col);
                if (row0 < M) {
                    float2 o;
                    o.x = acc[mi][ni][0] + bb.x;
                    o.y = acc[mi][ni][1] + bb.y;
                    *(float2*)(out + (size_t)row0 * NOUT + col) = o;
                }
                if (row1 < M) {
                    float2 o;
                    o.x = acc[mi][ni][2] + bb.x;
                    o.y = acc[mi][ni][3] + bb.y;
                    *(float2*)(out + (size_t)row1 * NOUT + col) = o;
                }
            }
        }

        __syncthreads();     // An fully written; Abuf[cur] reads done
        cur ^= 1;
    }
}

} // namespace

extern "C" void kernel_launch(void* const* d_in, const int* in_sizes, int n_in,
                              void* d_out, int out_size)
{
    const float* V   = (const float*)d_in[0];
    const float* E   = (const float*)d_in[1];
    const int*   EI  = (const int*)d_in[2];   // int32 (JAX canonicalized), row 0 = src
    const float* W   = (const float*)d_in[3];
    const float* b   = (const float*)d_in[4];
    float*       out = (float*)d_out;

    const int M = in_sizes[1] / BOND;
    const int ntiles = (M + BM - 1) / BM;

    int sms = 148;
    cudaDeviceGetAttribute(&sms, cudaDevAttrMultiProcessorCount, 0);
    int grid = sms < ntiles ? sms : ntiles;

    cudaFuncSetAttribute(bond_msg_kernel,
                         cudaFuncAttributeMaxDynamicSharedMemorySize, SMEM_BYTES);
    bond_msg_kernel<<<grid, NTHREADS, SMEM_BYTES>>>(V, E, EI, W, b, out, M, ntiles);
}

// round 10
// speedup vs baseline: 1.1548x; 1.1297x over previous
#include <cuda_runtime.h>
#include <cuda_fp16.h>
#include <cstdint>

namespace {

constexpr int ATOM = 128;
constexpr int BOND = 64;
constexpr int KTOT = 192;    // 48 float4 per row
constexpr int NOUT = 256;
constexpr int BM   = 128;    // edges per tile
constexpr int NTHREADS = 512;
constexpr int STRIDE = 100;  // row stride (words); %32=4 -> conflict-free frag LDS

// smem layout (4B words): B first, then two A buffers
constexpr int SM_B_W  = 0;                        // 256 x 100
constexpr int SM_A0_W = NOUT * STRIDE;            // 128 x 100
constexpr int SM_A1_W = SM_A0_W + BM * STRIDE;
constexpr int SMEM_BYTES = (SM_A1_W + BM * STRIDE) * 4;   // 204800

__device__ __forceinline__ uint32_t h2(float lo, float hi) {
    __half2 h = __floats2half2_rn(lo, hi);
    return *(uint32_t*)&h;
}

__global__ void __launch_bounds__(NTHREADS, 1)
bond_msg_kernel(const float* __restrict__ V,
                const float* __restrict__ E,
                const int* __restrict__ src0,      // edge_index row 0 (int32)
                const float* __restrict__ W,       // [NOUT, KTOT]
                const float* __restrict__ bias,    // [NOUT]
                float* __restrict__ out,           // [M, NOUT]
                int M, int ntiles)
{
    extern __shared__ uint32_t smem[];
    uint32_t* Bs = smem + SM_B_W;
    uint32_t* Abuf[2] = { smem + SM_A0_W, smem + SM_A1_W };

    const int tid  = threadIdx.x;
    const int lane = tid & 31;
    const int wid  = tid >> 5;
    const int warp_m = wid >> 2;   // 0..3 -> quarter-group; 32 A rows each
    const int warp_n = wid & 3;    // 0..3 (64 cols each)
    const int lr = lane >> 2;
    const int lc = lane & 3;
    const int gtid = tid & 127;    // tid within the 128-thread quarter-group
    const int G  = gridDim.x;

    // ---- Fill W once per CTA (persistent): 12288 float4, 24 per thread.
    #pragma unroll
    for (int i = 0; i < 24; ++i) {
        int idx = tid + i * NTHREADS;
        int n  = idx / 48;
        int c4 = idx % 48;
        float4 v = *(const float4*)(W + (size_t)n * KTOT + c4 * 4);
        uint32_t* d = Bs + n * STRIDE + c4 * 2;
        d[0] = h2(v.x, v.y);
        d[1] = h2(v.z, v.w);
    }

    // ---- Prologue: fill A[0] for the first tile (group-local rows).
    int t0 = blockIdx.x;
    if (t0 < ntiles) {
        int e0 = t0 * BM;
        #pragma unroll
        for (int i = 0; i < 12; ++i) {
            int idx = gtid + i * 128;          // 0..1535 within group
            int r  = warp_m * 32 + idx / 48;   // group fills its own 32 rows
            int c4 = idx % 48;
            int e  = e0 + r; if (e >= M) e = M - 1;
            const float* p = (c4 < 32)
                ? (V + (size_t)__ldg(src0 + e) * ATOM + c4 * 4)
                : (E + (size_t)e * BOND + (c4 - 32) * 4);
            float4 v = *(const float4*)p;
            uint32_t* d = Abuf[0] + r * STRIDE + c4 * 2;
            d[0] = h2(v.x, v.y);
            d[1] = h2(v.z, v.w);
        }
    }
    __syncthreads();   // W + first A visible to everyone

    int cur = 0;
    for (int t = t0; t < ntiles; t += G) {
        const int e0  = t * BM;
        const int tn  = t + G;
        const bool hn = (tn < ntiles);
        const int e0n = tn * BM;
        const uint32_t* Ac = Abuf[cur];
        uint32_t* An = Abuf[cur ^ 1];

        float acc[2][8][4];
        #pragma unroll
        for (int mi = 0; mi < 2; ++mi)
            #pragma unroll
            for (int ni = 0; ni < 8; ++ni)
                #pragma unroll
                for (int c = 0; c < 4; ++c)
                    acc[mi][ni][c] = 0.f;

        // 3 pipeline stages: prefetch batch b (4 float4, group-local rows)
        // -> 4 MMA k-steps -> STS batch b
        #pragma unroll
        for (int b = 0; b < 3; ++b) {
            float4 g[4];
            int gr[4], gc[4];
            if (hn) {
                #pragma unroll
                for (int i = 0; i < 4; ++i) {
                    int idx = gtid + (b * 4 + i) * 128;   // 0..1535
                    gr[i] = warp_m * 32 + idx / 48;
                    gc[i] = idx % 48;
                    int e = e0n + gr[i]; if (e >= M) e = M - 1;
                    const float* p = (gc[i] < 32)
                        ? (V + (size_t)__ldg(src0 + e) * ATOM + gc[i] * 4)
                        : (E + (size_t)e * BOND + (gc[i] - 32) * 4);
                    g[i] = *(const float4*)p;
                }
            }

            #pragma unroll
            for (int kk = b * 4; kk < b * 4 + 4; ++kk) {
                const int kb = kk * 8;
                uint32_t a[2][4], bf[8][2];
                #pragma unroll
                for (int mi = 0; mi < 2; ++mi) {
                    int r = warp_m * 32 + mi * 16 + lr;
                    const uint32_t* ap = Ac + r * STRIDE + kb;
                    a[mi][0] = ap[lc];
                    a[mi][1] = ap[8 * STRIDE + lc];
                    a[mi][2] = ap[lc + 4];
                    a[mi][3] = ap[8 * STRIDE + lc + 4];
                }
                #pragma unroll
                for (int ni = 0; ni < 8; ++ni) {
                    int n = warp_n * 64 + ni * 8 + lr;
                    const uint32_t* bp = Bs + n * STRIDE + kb;
                    bf[ni][0] = bp[lc];
                    bf[ni][1] = bp[lc + 4];
                }
                #pragma unroll
                for (int mi = 0; mi < 2; ++mi)
                    #pragma unroll
                    for (int ni = 0; ni < 8; ++ni) {
                        asm volatile(
                            "mma.sync.aligned.m16n8k16.row.col.f32.f16.f16.f32 "
                            "{%0,%1,%2,%3}, {%4,%5,%6,%7}, {%8,%9}, {%0,%1,%2,%3};\n"
                            : "+f"(acc[mi][ni][0]), "+f"(acc[mi][ni][1]),
                              "+f"(acc[mi][ni][2]), "+f"(acc[mi][ni][3])
                            : "r"(a[mi][0]), "r"(a[mi][1]),
                              "r"(a[mi][2]), "r"(a[mi][3]),
                              "r"(bf[ni][0]), "r"(bf[ni][1]));
                    }
            }

            if (hn) {
                #pragma unroll
                for (int i = 0; i < 4; ++i) {
                    uint32_t* d = An + gr[i] * STRIDE + gc[i] * 2;
                    d[0] = h2(g[i].x, g[i].y);
                    d[1] = h2(g[i].z, g[i].w);
                }
            }
        }

        // ---- Direct epilogue: fire-and-forget float2 STGs (no smem).
        #pragma unroll
        for (int mi = 0; mi < 2; ++mi) {
            int row0 = e0 + warp_m * 32 + mi * 16 + lr;
            int row1 = row0 + 8;
            #pragma unroll
            for (int ni = 0; ni < 8; ++ni) {
                int col = warp_n * 64 + ni * 8 + 2 * lc;
                float2 bb = *(const float2*)(bias + col);
                if (row0 < M) {
                    float2 o;
                    o.x = acc[mi][ni][0] + bb.x;
                    o.y = acc[mi][ni][1] + bb.y;
                    *(float2*)(out + (size_t)row0 * NOUT + col) = o;
                }
                if (row1 < M) {
                    float2 o;
                    o.x = acc[mi][ni][2] + bb.x;
                    o.y = acc[mi][ni][3] + bb.y;
                    *(float2*)(out + (size_t)row1 * NOUT + col) = o;
                }
            }
        }

        // Quarter-group barrier: A rows [32*warp_m, +32) are produced and
        // consumed ONLY by this 128-thread group -> no full-CTA sync needed.
        asm volatile("bar.sync %0, %1;" :: "r"(warp_m + 1), "r"(128) : "memory");
        cur ^= 1;
    }
}

} // namespace

extern "C" void kernel_launch(void* const* d_in, const int* in_sizes, int n_in,
                              void* d_out, int out_size)
{
    const float* V   = (const float*)d_in[0];
    const float* E   = (const float*)d_in[1];
    const int*   EI  = (const int*)d_in[2];   // int32 (JAX canonicalized), row 0 = src
    const float* W   = (const float*)d_in[3];
    const float* b   = (const float*)d_in[4];
    float*       out = (float*)d_out;

    const int M = in_sizes[1] / BOND;
    const int ntiles = (M + BM - 1) / BM;

    int sms = 148;
    cudaDeviceGetAttribute(&sms, cudaDevAttrMultiProcessorCount, 0);
    int grid = sms < ntiles ? sms : ntiles;

    cudaFuncSetAttribute(bond_msg_kernel,
                         cudaFuncAttributeMaxDynamicSharedMemorySize, SMEM_BYTES);
    bond_msg_kernel<<<grid, NTHREADS, SMEM_BYTES>>>(V, E, EI, W, b, out, M, ntiles);
}